// round 14
// baseline (speedup 1.0000x reference)
#include <cuda_runtime.h>
#include <cuda_bf16.h>
#include <cuda_fp16.h>
#include <cstdint>

#define NN   50000
#define EE   800000
#define FIN  128
#define HIDD 64
#define C1   192          // P*HID
#define EPSB 1e-5f
#define SCAN_B 196        // ceil(NN/256)
#define EPT  4            // edges per thread in count/fill

// ---------------- static device scratch (no allocations allowed) ----------------
__device__ __align__(256) __half g_Zh [(size_t)NN * 128];   // fp16 cols 64..191 of layer GEMM out
__device__ __align__(256) __half g_Th [(size_t)NN * HIDD];  // fp16 hop-1 intermediate
__device__ __align__(256) float g_Hpre[(size_t)NN * C1];    // fp32 layer-1 concat
__device__ __align__(256) float g_H2  [(size_t)NN * C1];    // fp32 layer-2 concat
__device__ int   g_cnt[NN];
__device__ int   g_rowptr[NN + 1];
__device__ int   g_pos[NN];
__device__ int   g_bsum[SCAN_B];
__device__ __align__(256) int2  g_edge[EE];        // {col, w as float bits}
__device__ float g_dinv[NN];
// two stat buffers (layer1 / layer2); each: [0..C1) sums, [C1..2C1) sumsq
__device__ __align__(256) float g_stats[2][2 * C1];

// ---------------- per-block dtype sniff (int64 vs int32 edge_index) -------------
__device__ __forceinline__ int sniff_is64(const long long* e, int* sFlag) {
    if (threadIdx.x < 32) {
        int bad = 0;
        #pragma unroll
        for (int l = 0; l < 2; l++) {
            long long v = e[threadIdx.x + 32 * l];
            bad |= (v < 0 || v >= NN);
        }
        unsigned m = __ballot_sync(0xffffffffu, bad);
        if (threadIdx.x == 0) *sFlag = (m == 0u);
    }
    __syncthreads();
    return *sFlag;
}

__device__ __forceinline__ int edge_at(const void* p, long long i, int is64) {
    if (is64) return (int)((const long long*)p)[i];
    return ((const int*)p)[i];
}

// ---------------- graph preprocessing (EPT edges/thread for MLP) ----------------
__global__ void k_count(const void* e) {
    __shared__ int sIs64;
    int is64 = sniff_is64((const long long*)e, &sIs64);
    int i0 = (blockIdx.x * blockDim.x + threadIdx.x) * EPT;
    int d[EPT];
    #pragma unroll
    for (int j = 0; j < EPT; j++)
        d[j] = (i0 + j < EE) ? edge_at(e, (long long)EE + i0 + j, is64) : -1;
    #pragma unroll
    for (int j = 0; j < EPT; j++)
        if (d[j] >= 0) atomicAdd(&g_cnt[d[j]], 1);
}

__global__ void k_bsum() {
    __shared__ int sh[256];
    int i = blockIdx.x * 256 + threadIdx.x;
    sh[threadIdx.x] = (i < NN) ? g_cnt[i] : 0;
    __syncthreads();
    for (int s = 128; s > 0; s >>= 1) {
        if (threadIdx.x < s) sh[threadIdx.x] += sh[threadIdx.x + s];
        __syncthreads();
    }
    if (threadIdx.x == 0) g_bsum[blockIdx.x] = sh[0];
}

// fused: redundant per-block scan of the 196 block sums + local scan + dinv
__global__ void k_scan_final() {
    __shared__ int sb[256];
    __shared__ int sh[256];
    int t = threadIdx.x;
    int bv = (t < SCAN_B) ? g_bsum[t] : 0;
    sb[t] = bv;
    __syncthreads();
    for (int off = 1; off < 256; off <<= 1) {
        int tv = (t >= off) ? sb[t - off] : 0;
        __syncthreads();
        sb[t] += tv;
        __syncthreads();
    }
    int blockOff = (blockIdx.x == 0) ? 0 : sb[blockIdx.x - 1];
    int i = blockIdx.x * 256 + t;
    int v = (i < NN) ? g_cnt[i] : 0;
    sh[t] = v;
    __syncthreads();
    for (int off = 1; off < 256; off <<= 1) {
        int tv = (t >= off) ? sh[t - off] : 0;
        __syncthreads();
        sh[t] += tv;
        __syncthreads();
    }
    int excl = sh[t] - v + blockOff;
    if (i < NN) {
        g_rowptr[i] = excl;
        g_pos[i]    = excl;
        g_dinv[i]   = rsqrtf((float)v + 1.0f);   // +1 self loop
    }
    if (blockIdx.x == 0 && t == 0) g_rowptr[NN] = EE;
}

__global__ void k_fill(const void* e) {
    __shared__ int sIs64;
    int is64 = sniff_is64((const long long*)e, &sIs64);
    int i0 = (blockIdx.x * blockDim.x + threadIdx.x) * EPT;
    int s[EPT], d[EPT];
    #pragma unroll
    for (int j = 0; j < EPT; j++) {
        int i = i0 + j;
        if (i < EE) {
            s[j] = edge_at(e, i, is64);
            d[j] = edge_at(e, (long long)EE + i, is64);
        } else { s[j] = -1; d[j] = 0; }
    }
    float ds[EPT], dd[EPT];
    #pragma unroll
    for (int j = 0; j < EPT; j++) {
        ds[j] = (s[j] >= 0) ? g_dinv[s[j]] : 0.f;
        dd[j] = (s[j] >= 0) ? g_dinv[d[j]] : 0.f;
    }
    #pragma unroll
    for (int j = 0; j < EPT; j++) {
        if (s[j] >= 0) {
            int p = atomicAdd(&g_pos[d[j]], 1);
            int2 ew;
            ew.x = s[j];
            ew.y = __float_as_int(ds[j] * dd[j]);
            g_edge[p] = ew;
        }
    }
}

// ------- hop 1: gather fp16 Zh rows; power-1 -> H fp32 (+stats), A*z2 -> Th ----
__global__ __launch_bounds__(256) void spmm128h(
    const __half* __restrict__ Zh, float* __restrict__ H, __half* __restrict__ Th,
    float* __restrict__ stats)
{
    __shared__ float sS[64], sQ[64];
    if (threadIdx.x < 64) { sS[threadIdx.x] = 0.f; sQ[threadIdx.x] = 0.f; }
    __syncthreads();

    int warp = (blockIdx.x * blockDim.x + threadIdx.x) >> 5;
    int lane = threadIdx.x & 31;
    float dv = g_dinv[warp];
    float ws = dv * dv;
    uint2 zp = ((const uint2*)(Zh + (size_t)warp * 128))[lane];     // 4 halves
    float2 z0 = __half22float2(*(const __half2*)&zp.x);
    float2 z1 = __half22float2(*(const __half2*)&zp.y);
    float a0 = ws * z0.x, a1 = ws * z0.y, a2 = ws * z1.x, a3 = ws * z1.y;
    int e0 = g_rowptr[warp], e1 = g_rowptr[warp + 1];
    #pragma unroll 4
    for (int e = e0; e < e1; e++) {
        int2 ew  = __ldg(&g_edge[e]);
        int c    = ew.x;
        float wt = __int_as_float(ew.y);
        uint2 vp = ((const uint2*)(Zh + (size_t)c * 128))[lane];
        float2 v0 = __half22float2(*(const __half2*)&vp.x);
        float2 v1 = __half22float2(*(const __half2*)&vp.y);
        a0 = fmaf(wt, v0.x, a0);
        a1 = fmaf(wt, v0.y, a1);
        a2 = fmaf(wt, v1.x, a2);
        a3 = fmaf(wt, v1.y, a3);
    }
    if (lane < 16) {
        float4 o; o.x = a0; o.y = a1; o.z = a2; o.w = a3;
        *(float4*)(H + (size_t)warp * C1 + HIDD + lane * 4) = o;
        int b = lane * 4;
        atomicAdd(&sS[b + 0], a0); atomicAdd(&sQ[b + 0], a0 * a0);
        atomicAdd(&sS[b + 1], a1); atomicAdd(&sQ[b + 1], a1 * a1);
        atomicAdd(&sS[b + 2], a2); atomicAdd(&sQ[b + 2], a2 * a2);
        atomicAdd(&sS[b + 3], a3); atomicAdd(&sQ[b + 3], a3 * a3);
    } else {
        uint2 op;
        *(__half2*)&op.x = __floats2half2_rn(a0, a1);
        *(__half2*)&op.y = __floats2half2_rn(a2, a3);
        *(uint2*)(Th + (size_t)warp * HIDD + (lane - 16) * 4) = op;
    }
    __syncthreads();
    if (threadIdx.x < 64) {
        atomicAdd(&stats[HIDD + threadIdx.x], sS[threadIdx.x]);
        atomicAdd(&stats[C1 + HIDD + threadIdx.x], sQ[threadIdx.x]);
    }
}

// ------- hop 2: gather fp16 Th rows; power-2 -> H fp32 (+stats) -----------------
__global__ __launch_bounds__(256) void spmm64h(
    const __half* __restrict__ Th, float* __restrict__ H, float* __restrict__ stats)
{
    __shared__ float sS[64], sQ[64];
    if (threadIdx.x < 64) { sS[threadIdx.x] = 0.f; sQ[threadIdx.x] = 0.f; }
    __syncthreads();

    int warp = (blockIdx.x * blockDim.x + threadIdx.x) >> 5;
    int lane = threadIdx.x & 31;
    float dv = g_dinv[warp];
    float ws = dv * dv;
    uint32_t zp = ((const uint32_t*)(Th + (size_t)warp * HIDD))[lane];
    float2 z = __half22float2(*(const __half2*)&zp);
    float ax = ws * z.x, ay = ws * z.y;
    int e0 = g_rowptr[warp], e1 = g_rowptr[warp + 1];
    #pragma unroll 4
    for (int e = e0; e < e1; e++) {
        int2 ew  = __ldg(&g_edge[e]);
        int c    = ew.x;
        float wt = __int_as_float(ew.y);
        uint32_t vp = ((const uint32_t*)(Th + (size_t)c * HIDD))[lane];
        float2 v = __half22float2(*(const __half2*)&vp);
        ax = fmaf(wt, v.x, ax);
        ay = fmaf(wt, v.y, ay);
    }
    float2 o; o.x = ax; o.y = ay;
    *(float2*)(H + (size_t)warp * C1 + 2 * HIDD + lane * 2) = o;
    int b = lane * 2;
    atomicAdd(&sS[b + 0], ax); atomicAdd(&sQ[b + 0], ax * ax);
    atomicAdd(&sS[b + 1], ay); atomicAdd(&sQ[b + 1], ay * ay);
    __syncthreads();
    if (threadIdx.x < 64) {
        atomicAdd(&stats[2 * HIDD + threadIdx.x], sS[threadIdx.x]);
        atomicAdd(&stats[C1 + 2 * HIDD + threadIdx.x], sQ[threadIdx.x]);
    }
}

// ------------- bf16 split-2 tensor-core GEMM (m16n8k16, 3-term compensation) ----
// A fp32. BN+ReLU on A from statsIn when gvec. Register-prefetch pipelined.
// p==0: fp32 store into dup (ld C1) + power-0 stats into statsOut.
// p>=1: fp16 store into zh (ld 128). C fp32 (ld NC) if non-null.
#define BM 128
#define BN 64
#define BK 32
#define KP 16
#define AST 20
#define BST 72

__device__ __forceinline__ uint32_t pack_bf16(float x, float y) {
    __nv_bfloat162 t;
    t.x = __float2bfloat16_rn(x);
    t.y = __float2bfloat16_rn(y);
    return *reinterpret_cast<uint32_t*>(&t);
}
__device__ __forceinline__ float bf_hi_f(float x) {
    return __bfloat162float(__float2bfloat16_rn(x));
}

__device__ __forceinline__ void mma_bf16(float* d, const uint32_t* a, const uint32_t* b) {
    asm volatile(
        "mma.sync.aligned.m16n8k16.row.col.f32.bf16.bf16.f32 "
        "{%0,%1,%2,%3},{%4,%5,%6,%7},{%8,%9},{%0,%1,%2,%3};\n"
        : "+f"(d[0]), "+f"(d[1]), "+f"(d[2]), "+f"(d[3])
        : "r"(a[0]), "r"(a[1]), "r"(a[2]), "r"(a[3]), "r"(b[0]), "r"(b[1]));
}

__global__ __launch_bounds__(256, 2) void tgemm(
    const float* __restrict__ A, const float* __restrict__ Bmat,
    float* __restrict__ C, int M, int K, int NC,
    const float* __restrict__ bias,
    const float* __restrict__ gvec, const float* __restrict__ bevec,
    const float* __restrict__ statsIn,
    float* __restrict__ dup, __half* __restrict__ zh,
    float* __restrict__ statsOut)
{
    __shared__ uint32_t AsH[BM * AST];
    __shared__ uint32_t AsL[BM * AST];
    __shared__ uint32_t BsH[KP * BST];
    __shared__ uint32_t BsL[KP * BST];
    __shared__ float sSc[C1];
    __shared__ float sSh[C1];
    __shared__ float sSum[64];
    __shared__ float sSq[64];
    int p = blockIdx.y;
    const float* Bp = Bmat + (size_t)p * K * BN;
    int rowBase = blockIdx.x * BM;
    int tid  = threadIdx.x;
    int lane = tid & 31;
    int w    = tid >> 5;
    int wm   = w & 3;
    int wn   = w >> 2;
    int lr   = lane >> 2;
    int lc   = lane & 3;

    bool hasbn = (gvec != nullptr);
    bool dostats = (statsOut != nullptr) && (p == 0);
    if (tid < 64) { sSum[tid] = 0.f; sSq[tid] = 0.f; }
    if (hasbn && tid < C1) {
        float mu  = statsIn[tid] * (1.0f / NN);
        float var = statsIn[C1 + tid] * (1.0f / NN) - mu * mu;
        float inv = rsqrtf(var + EPSB);
        float sc  = inv * gvec[tid];
        sSc[tid] = sc;
        sSh[tid] = bevec[tid] - mu * sc;
    }
    __syncthreads();

    const int ar  = tid >> 3;
    const int ac4 = tid & 7;
    const int bkp = tid >> 4;
    const int bn4 = tid & 15;

    float acc[2][4][4];
    #pragma unroll
    for (int mt = 0; mt < 2; mt++)
        #pragma unroll
        for (int nt = 0; nt < 4; nt++)
            #pragma unroll
            for (int i = 0; i < 4; i++) acc[mt][nt][i] = 0.f;

    float4 avA[4];
    float4 avB0, avB1;
    #pragma unroll
    for (int l = 0; l < 4; l++) {
        int grow = rowBase + ar + l * 32;
        avA[l] = (grow < M) ? *(const float4*)(A + (size_t)grow * K + ac4 * 4)
                            : make_float4(0.f, 0.f, 0.f, 0.f);
    }
    {
        const float* r0p = Bp + (size_t)(2 * bkp) * BN + bn4 * 4;
        avB0 = *(const float4*)r0p;
        avB1 = *(const float4*)(r0p + BN);
    }

    for (int k0 = 0; k0 < K; k0 += BK) {
        #pragma unroll
        for (int l = 0; l < 4; l++) {
            float4 v = avA[l];
            if (hasbn) {
                int kc = k0 + ac4 * 4;
                v.x = fmaxf(0.f, fmaf(v.x, sSc[kc + 0], sSh[kc + 0]));
                v.y = fmaxf(0.f, fmaf(v.y, sSc[kc + 1], sSh[kc + 1]));
                v.z = fmaxf(0.f, fmaf(v.z, sSc[kc + 2], sSh[kc + 2]));
                v.w = fmaxf(0.f, fmaf(v.w, sSc[kc + 3], sSh[kc + 3]));
            }
            int row = ar + l * 32;
            int kp  = ac4 * 2;
            AsH[row * AST + kp]     = pack_bf16(v.x, v.y);
            AsH[row * AST + kp + 1] = pack_bf16(v.z, v.w);
            AsL[row * AST + kp]     = pack_bf16(v.x - bf_hi_f(v.x), v.y - bf_hi_f(v.y));
            AsL[row * AST + kp + 1] = pack_bf16(v.z - bf_hi_f(v.z), v.w - bf_hi_f(v.w));
        }
        {
            float4 u0 = avB0, u1 = avB1;
            uint32_t* dh = &BsH[bkp * BST + bn4 * 4];
            uint32_t* dl = &BsL[bkp * BST + bn4 * 4];
            dh[0] = pack_bf16(u0.x, u1.x);
            dh[1] = pack_bf16(u0.y, u1.y);
            dh[2] = pack_bf16(u0.z, u1.z);
            dh[3] = pack_bf16(u0.w, u1.w);
            dl[0] = pack_bf16(u0.x - bf_hi_f(u0.x), u1.x - bf_hi_f(u1.x));
            dl[1] = pack_bf16(u0.y - bf_hi_f(u0.y), u1.y - bf_hi_f(u1.y));
            dl[2] = pack_bf16(u0.z - bf_hi_f(u0.z), u1.z - bf_hi_f(u1.z));
            dl[3] = pack_bf16(u0.w - bf_hi_f(u0.w), u1.w - bf_hi_f(u1.w));
        }
        __syncthreads();

        int kn = k0 + BK;
        if (kn < K) {
            #pragma unroll
            for (int l = 0; l < 4; l++) {
                int grow = rowBase + ar + l * 32;
                avA[l] = (grow < M) ? *(const float4*)(A + (size_t)grow * K + kn + ac4 * 4)
                                    : make_float4(0.f, 0.f, 0.f, 0.f);
            }
            const float* r0p = Bp + (size_t)(kn + 2 * bkp) * BN + bn4 * 4;
            avB0 = *(const float4*)r0p;
            avB1 = *(const float4*)(r0p + BN);
        }

        #pragma unroll
        for (int c = 0; c < 2; c++) {
            int kpb = c * 8;
            uint32_t ahi[2][4], alo[2][4];
            #pragma unroll
            for (int mt = 0; mt < 2; mt++) {
                int r0 = wm * 32 + mt * 16 + lr;
                ahi[mt][0] = AsH[r0 * AST + kpb + lc];
                ahi[mt][1] = AsH[(r0 + 8) * AST + kpb + lc];
                ahi[mt][2] = AsH[r0 * AST + kpb + lc + 4];
                ahi[mt][3] = AsH[(r0 + 8) * AST + kpb + lc + 4];
                alo[mt][0] = AsL[r0 * AST + kpb + lc];
                alo[mt][1] = AsL[(r0 + 8) * AST + kpb + lc];
                alo[mt][2] = AsL[r0 * AST + kpb + lc + 4];
                alo[mt][3] = AsL[(r0 + 8) * AST + kpb + lc + 4];
            }
            uint32_t bhi[4][2], blo[4][2];
            #pragma unroll
            for (int nt = 0; nt < 4; nt++) {
                int n0 = wn * 32 + nt * 8 + lr;
                bhi[nt][0] = BsH[(kpb + lc) * BST + n0];
                bhi[nt][1] = BsH[(kpb + lc + 4) * BST + n0];
                blo[nt][0] = BsL[(kpb + lc) * BST + n0];
                blo[nt][1] = BsL[(kpb + lc + 4) * BST + n0];
            }
            #pragma unroll
            for (int mt = 0; mt < 2; mt++)
                #pragma unroll
                for (int nt = 0; nt < 4; nt++) {
                    mma_bf16(acc[mt][nt], ahi[mt], bhi[nt]);
                    mma_bf16(acc[mt][nt], ahi[mt], blo[nt]);
                    mma_bf16(acc[mt][nt], alo[mt], bhi[nt]);
                }
        }
        __syncthreads();
    }

    #pragma unroll
    for (int nt = 0; nt < 4; nt++) {
        int ncol = wn * 32 + nt * 8 + lc * 2;
        int gcol = p * BN + ncol;
        float bx = 0.f, by = 0.f;
        if (bias) { bx = bias[ncol]; by = bias[ncol + 1]; }
        float psx = 0.f, psy = 0.f, pqx = 0.f, pqy = 0.f;
        #pragma unroll
        for (int mt = 0; mt < 2; mt++) {
            #pragma unroll
            for (int hh = 0; hh < 2; hh++) {
                int r = rowBase + wm * 32 + mt * 16 + lr + hh * 8;
                if (r < M) {
                    float ox = acc[mt][nt][2 * hh]     + bx;
                    float oy = acc[mt][nt][2 * hh + 1] + by;
                    if (C) {
                        float2 o; o.x = ox; o.y = oy;
                        *(float2*)(C + (size_t)r * NC + gcol) = o;
                    }
                    if (p == 0) {
                        if (dup) {
                            float2 o; o.x = ox; o.y = oy;
                            *(float2*)(dup + (size_t)r * C1 + gcol) = o;
                        }
                    } else if (zh) {
                        *(__half2*)(zh + (size_t)r * 128 + (gcol - BN)) = __floats2half2_rn(ox, oy);
                    }
                    if (dostats) {
                        psx += ox; pqx = fmaf(ox, ox, pqx);
                        psy += oy; pqy = fmaf(oy, oy, pqy);
                    }
                }
            }
        }
        if (dostats) {
            atomicAdd(&sSum[ncol],     psx); atomicAdd(&sSq[ncol],     pqx);
            atomicAdd(&sSum[ncol + 1], psy); atomicAdd(&sSq[ncol + 1], pqy);
        }
    }
    if (dostats) {
        __syncthreads();
        if (tid < 64) {
            atomicAdd(&statsOut[tid],      sSum[tid]);
            atomicAdd(&statsOut[C1 + tid], sSq[tid]);
        }
    }
}

// ---------------- host launch ----------------
extern "C" void kernel_launch(void* const* d_in, const int* in_sizes, int n_in,
                              void* d_out, int out_size) {
    const float* x   = (const float*)d_in[0];
    const void*  ei  = d_in[1];
    const float* W1  = (const float*)d_in[2];
    // d_in[3] = B1 (absorbed by BatchNorm)
    const float* g1  = (const float*)d_in[4];
    const float* be1 = (const float*)d_in[5];
    const float* W2  = (const float*)d_in[6];
    // d_in[7] = B2 (absorbed by BatchNorm)
    const float* g2  = (const float*)d_in[8];
    const float* be2 = (const float*)d_in[9];
    const float* Wfc = (const float*)d_in[10];
    const float* bfc = (const float*)d_in[11];
    float* out = (float*)d_out;

    float *Hpre, *H2, *St;
    __half *Zh, *Th;
    int *Cnt;
    cudaGetSymbolAddress((void**)&Zh,   g_Zh);
    cudaGetSymbolAddress((void**)&Th,   g_Th);
    cudaGetSymbolAddress((void**)&Hpre, g_Hpre);
    cudaGetSymbolAddress((void**)&H2,   g_H2);
    cudaGetSymbolAddress((void**)&St,   g_stats);
    cudaGetSymbolAddress((void**)&Cnt,  g_cnt);
    float* StA = St;
    float* StB = St + 2 * C1;

    static cudaStream_t sB = nullptr;
    static cudaEvent_t evFork = nullptr, evJoin = nullptr;
    if (!sB) {
        cudaStreamCreateWithFlags(&sB, cudaStreamNonBlocking);
        cudaEventCreateWithFlags(&evFork, cudaEventDisableTiming);
        cudaEventCreateWithFlags(&evJoin, cudaEventDisableTiming);
    }

    const int TB = 256;
    const int nBlkEdge = (EE + TB * EPT - 1) / (TB * EPT);
    const int nBlkSp   = (NN + 7) / 8;
    const dim3 gemmG((NN + BM - 1) / BM, 3);
    const dim3 gemmO((NN + BM - 1) / BM, 1);

    // zero both stat buffers once (3 KB) before any producer runs
    cudaMemsetAsync(St, 0, 4 * C1 * sizeof(float));

    // ---- fork: CSR preprocessing on side stream, layer-1 GEMM on main --------
    cudaEventRecord(evFork, 0);
    cudaStreamWaitEvent(sB, evFork, 0);

    cudaMemsetAsync(Cnt, 0, NN * sizeof(int), sB);
    k_count<<<nBlkEdge, TB, 0, sB>>>(ei);
    k_bsum<<<SCAN_B, 256, 0, sB>>>();
    k_scan_final<<<SCAN_B, 256, 0, sB>>>();
    k_fill<<<nBlkEdge, TB, 0, sB>>>(ei);
    cudaEventRecord(evJoin, sB);

    // main stream: layer-1 GEMM (power0 -> Hpre fp32 + stats into StA; Zh fp16)
    tgemm<<<gemmG, TB>>>(x, W1, nullptr, NN, FIN, C1, nullptr,
                         nullptr, nullptr, nullptr, Hpre, Zh, StA);

    cudaStreamWaitEvent(0, evJoin, 0);                // join: SpMM needs CSR + Zh

    // ---- layer 1 propagation (stats fused) ----
    spmm128h<<<nBlkSp, TB>>>(Zh, Hpre, Th, StA);
    spmm64h<<<nBlkSp, TB>>>(Th, Hpre, StA);

    // ---- layer 2 (BN1+ReLU from StA; power0 stats -> StB) ----
    tgemm<<<gemmG, TB>>>(Hpre, W2, nullptr, NN, C1, C1, nullptr,
                         g1, be1, StA, H2, Zh, StB);
    spmm128h<<<nBlkSp, TB>>>(Zh, H2, Th, StB);
    spmm64h<<<nBlkSp, TB>>>(Th, H2, StB);

    // ---- final fc (BN2+ReLU from StB) ----
    tgemm<<<gemmO, TB>>>(H2, Wfc, out, NN, C1, HIDD, bfc,
                         g2, be2, StB, nullptr, nullptr, nullptr);

    (void)in_sizes; (void)n_in; (void)out_size;
}